// round 9
// baseline (speedup 1.0000x reference)
#include <cuda_runtime.h>
#include <cuda_fp16.h>
#include <math.h>
#include <stdint.h>

#define HH    512
#define NPIX  (HH*HH)
#define FD    128
#define NR    363
#define BM    32
#define GEMM_THREADS 256
#define GEMM_GRID 296      // 2 per SM
#define HALF_GRID (GEMM_GRID/2)

// k_gemm smem layout (2 CTAs/SM): exactly 112KB
#define OFF_A    0
#define SEGA     8192                        // 32 rows x 256B fp16
#define OFF_B    (2*SEGA)                    // 16384
#define MATB     32768                       // 128n x 256B fp16
#define SMEM_TOTAL (OFF_B + 3*MATB)          // 114688 = 112KB exact

// ---------------- device scratch ----------------
__device__ float g_sum_re[NR*FD];
__device__ float g_sum_im[NR*FD];
__device__ float g_mean_re[NR*FD];
__device__ float g_mean_im[NR*FD];
__device__ int   g_rcount[NR];
__device__ int   g_ucnt[NR];
__device__ int   g_base[NR+1];
__device__ int   g_cur[NR+1];
__device__ int   g_cnt[2];
__device__ int   g_list[2][NPIX];
// per type: 0=Wr, 1=Wm(Wi-Wr), 2=Wp(Wi+Wr), transposed [n*128+k] fp16
__device__ __align__(16) __half g_W3[2][3][FD*FD];

// ---------------- helpers ----------------
__device__ __forceinline__ int ring_of(int p) {
    int i = (p >> 9) - 256;
    int j = (p & 511) - 256;
    int q = i*i + j*j;
    int s = __float2int_rd(sqrtf((float)q));
    while (s*s > q) --s;
    while ((s+1)*(s+1) <= q) ++s;
    return s;
}

__device__ __forceinline__ uint32_t smem_u32(const void* p) {
    uint32_t a;
    asm("{ .reg .u64 t; cvta.to.shared.u64 t, %1; cvt.u32.u64 %0, t; }" : "=r"(a) : "l"(p));
    return a;
}

// 16B-unit XOR swizzle within 256B rows
__device__ __forceinline__ int phys_unit(int u, int row) {
    return (u & 8) | ((u & 7) ^ (row & 7));
}

#define LDSM_X4(r, addr) \
    asm volatile("ldmatrix.sync.aligned.m8n8.x4.shared.b16 {%0,%1,%2,%3}, [%4];" \
        : "=r"((r)[0]), "=r"((r)[1]), "=r"((r)[2]), "=r"((r)[3]) : "r"(addr))

__device__ __forceinline__ void mma4(float* d, const uint32_t* a, uint32_t b0, uint32_t b1) {
    asm volatile("mma.sync.aligned.m16n8k16.row.col.f32.f16.f16.f32 "
        "{%0,%1,%2,%3}, {%4,%5,%6,%7}, {%8,%9}, {%0,%1,%2,%3};"
        : "+f"(d[0]), "+f"(d[1]), "+f"(d[2]), "+f"(d[3])
        : "r"(a[0]), "r"(a[1]), "r"(a[2]), "r"(a[3]), "r"(b0), "r"(b1));
}

// ---------------- merged zero + Gauss weight prep ----------------
__global__ void k_prep(const float* __restrict__ w1re, const float* __restrict__ w1im,
                       const float* __restrict__ w2re, const float* __restrict__ w2im) {
    int idx = blockIdx.x * blockDim.x + threadIdx.x;   // 2 types x 16384
    if (idx < NR) { g_rcount[idx] = 0; g_ucnt[idx] = 0; }
    if (idx >= 2*FD*FD) return;
    int type = idx >> 14;
    int rem = idx & (FD*FD - 1);
    int n = rem >> 7, k = rem & 127;
    const float* Wre = type ? w2re : w1re;
    const float* Wim = type ? w2im : w1im;
    float wr = Wre[k*FD + n];
    float wi = Wim[k*FD + n];
    g_W3[type][0][n*FD + k] = __float2half_rn(wr);
    g_W3[type][1][n*FD + k] = __float2half_rn(wi - wr);
    g_W3[type][2][n*FD + k] = __float2half_rn(wi + wr);
}

__global__ void k_count(const int* __restrict__ mask) {
    __shared__ int scnt[2*NR];
    int t = threadIdx.x;
    for (int i = t; i < 2*NR; i += 256) scnt[i] = 0;
    __syncthreads();
    int base = blockIdx.x * 1024;
    #pragma unroll
    for (int i = 0; i < 4; i++) {
        int p = base + i*256 + t;
        int r = ring_of(p);
        int m = mask[p];
        atomicAdd(&scnt[r], 1);
        if (m == 0) atomicAdd(&scnt[NR + r], 1);
    }
    __syncthreads();
    for (int i = t; i < NR; i += 256) {
        int c = scnt[i];       if (c) atomicAdd(&g_rcount[i], c);
        int u = scnt[NR + i];  if (u) atomicAdd(&g_ucnt[i], u);
    }
}

__global__ void k_scan() {
    __shared__ int s[512];
    int t = threadIdx.x;
    int v = (t < NR) ? g_ucnt[t] : 0;
    s[t] = v;
    __syncthreads();
    #pragma unroll
    for (int d = 1; d < 512; d <<= 1) {
        int x = (t >= d) ? s[t - d] : 0;
        __syncthreads();
        s[t] += x;
        __syncthreads();
    }
    int base = (t == 0) ? 0 : s[t - 1];
    if (t < NR) { g_base[t] = base; g_cur[t] = base; }
    if (t == NR) {
        g_base[NR] = base;
        g_cur[NR]  = 0;
        g_cnt[0]   = base;
        g_cnt[1]   = NPIX - base;
    }
}

__global__ void k_scatter(const int* __restrict__ mask) {
    __shared__ int lcnt[NR+1];
    __shared__ int sbase[NR+1];
    int t = threadIdx.x;
    for (int i = t; i < NR+1; i += 256) lcnt[i] = 0;
    __syncthreads();
    int base = blockIdx.x * 1024;
    int key[4], lpos[4];
    #pragma unroll
    for (int i = 0; i < 4; i++) {
        int p = base + i*256 + t;
        int m = mask[p];
        key[i] = m ? NR : ring_of(p);
        lpos[i] = atomicAdd(&lcnt[key[i]], 1);
    }
    __syncthreads();
    for (int i = t; i < NR+1; i += 256) {
        int c = lcnt[i];
        if (c) sbase[i] = atomicAdd(&g_cur[i], c);
    }
    __syncthreads();
    #pragma unroll
    for (int i = 0; i < 4; i++) {
        int p = base + i*256 + t;
        int pos = sbase[key[i]] + lpos[i];
        if (key[i] == NR) g_list[1][pos] = p;
        else              g_list[0][pos] = p;
    }
}

// atomic-free ring sums: grid (NR, 8), block 128
__global__ void k_ringsum(const float* __restrict__ img_re,
                          const float* __restrict__ img_im) {
    __shared__ float sred[4][32];
    int r = blockIdx.x, g = blockIdx.y;
    int t = threadIdx.x, lane = t & 31, wid = t >> 5;
    int b0 = g_base[r], n = g_base[r+1] - b0;
    const int* lst = g_list[0] + b0;
    float ar[16], ai[16];
    #pragma unroll
    for (int f = 0; f < 16; f++) { ar[f] = 0.f; ai[f] = 0.f; }
    for (int i = t; i < n; i += 128) {
        int p = lst[i];
        const float4* pr = (const float4*)(img_re + (size_t)p*FD + g*16);
        const float4* pi = (const float4*)(img_im + (size_t)p*FD + g*16);
        #pragma unroll
        for (int c = 0; c < 4; c++) {
            float4 v = pr[c];
            ar[c*4+0] += v.x; ar[c*4+1] += v.y; ar[c*4+2] += v.z; ar[c*4+3] += v.w;
            v = pi[c];
            ai[c*4+0] += v.x; ai[c*4+1] += v.y; ai[c*4+2] += v.z; ai[c*4+3] += v.w;
        }
    }
    #pragma unroll
    for (int f = 0; f < 16; f++) {
        #pragma unroll
        for (int m = 16; m > 0; m >>= 1) {
            ar[f] += __shfl_xor_sync(0xFFFFFFFF, ar[f], m);
            ai[f] += __shfl_xor_sync(0xFFFFFFFF, ai[f], m);
        }
    }
    if (lane == 0) {
        #pragma unroll
        for (int f = 0; f < 16; f++) {
            sred[wid][f]      = ar[f];
            sred[wid][16 + f] = ai[f];
        }
    }
    __syncthreads();
    if (t < 32) {
        float s = sred[0][t] + sred[1][t] + sred[2][t] + sred[3][t];
        int f = t & 15;
        if (t < 16) g_sum_re[r*FD + g*16 + f] = s;
        else        g_sum_im[r*FD + g*16 + f] = s;
    }
}

// ring means: block 512 = 4 k-slices x 128 features
__global__ void k_ringmm(const float* __restrict__ w1re,
                         const float* __restrict__ w1im) {
    __shared__ float sre[FD], sim[FD];
    __shared__ float pre[4][FD], pim[4][FD];
    int r = blockIdx.x, t = threadIdx.x;
    int sl = t >> 7, f = t & 127;
    if (t < 256) {
        if (t < 128) sre[t] = g_sum_re[r*FD + t];
        else         sim[t - 128] = g_sum_im[r*FD + t - 128];
    }
    __syncthreads();
    float accr = 0.f, acci = 0.f;
    #pragma unroll 8
    for (int kk = 0; kk < 32; kk++) {
        int k = sl*32 + kk;
        float wr = w1re[k*FD + f];
        float wi = w1im[k*FD + f];
        accr += sre[k]*wr - sim[k]*wi;
        acci += sre[k]*wi + sim[k]*wr;
    }
    pre[sl][f] = accr;
    pim[sl][f] = acci;
    __syncthreads();
    if (t < 256) {
        float c = (float)max(g_rcount[r], 1);
        int ff = t & 127;
        if (t < 128) g_mean_re[r*FD + ff] = (pre[0][ff]+pre[1][ff]+pre[2][ff]+pre[3][ff]) / c;
        else         g_mean_im[r*FD + ff] = (pim[0][ff]+pim[1][ff]+pim[2][ff]+pim[3][ff]) / c;
    }
}

// ---------------- main GEMM: Gauss fp16 HMMA, precombined B, BM=32, 2 CTA/SM ----------------
// A segs: 0=Xr, 1=Xi; As derived in registers (4 HADD2/kstep)
// B mats: 0=Wr, 1=Wm(Wi-Wr), 2=Wp(Wi+Wr)
// T1=As@Wr, T2=Xr@Wm, T3=Xi@Wp; re=T1-T3, im=T1+T2
__global__ __launch_bounds__(GEMM_THREADS, 2)
void k_gemm(const float* __restrict__ img_re, const float* __restrict__ img_im,
            float* __restrict__ out) {
    extern __shared__ char sm[];
    const int t = threadIdx.x, lane = t & 31, wid = t >> 5;
    const int warp_m = wid >> 2;          // 0..1 (16 rows each)
    const int warp_n = wid & 3;           // 0..3 (32 cols each)

    const int type  = (blockIdx.x >= HALF_GRID) ? 1 : 0;
    const int bid_t = type ? blockIdx.x - HALF_GRID : blockIdx.x;
    const int cnt   = g_cnt[type];
    const int T     = (cnt + BM - 1) >> 5;
    const int* lst  = g_list[type];

    uint32_t smb = smem_u32(sm);
    const int row = t >> 3, q = t & 7;    // 8 threads per A row (32 rows)

    // ---- stage B: Wr, Wm, Wp fp16 transposed, swizzled (resident) ----
    {
        #pragma unroll 4
        for (int i = t; i < 3*2048; i += GEMM_THREADS) {
            int mat = i / 2048, g = i & 2047;
            int n = g >> 4, u = g & 15;
            uint4 v = ((const uint4*)g_W3[type][mat])[g];
            *(uint4*)(sm + OFF_B + mat*MATB + n*256 + phys_unit(u, n)*16) = v;
        }
    }

    for (int tile = bid_t; tile < T; tile += HALF_GRID) {
        __syncthreads();   // prev compute done before A rewrite

        // ---- stage A: Xr, Xi fp16, swizzled ----
        {
            int grow = tile*BM + row;
            int p = (grow < cnt) ? lst[grow] : -1;
            const float4* ar = (const float4*)(img_re + (size_t)(p < 0 ? 0 : p) * FD);
            const float4* ai = (const float4*)(img_im + (size_t)(p < 0 ? 0 : p) * FD);
            float4 z = make_float4(0.f, 0.f, 0.f, 0.f);
            #pragma unroll
            for (int i = 0; i < 4; i++) {
                int k4 = q*4 + i;
                int u  = k4 >> 1;
                uint32_t base = (uint32_t)(row*256 + phys_unit(u, row)*16 + (k4 & 1)*8);
                float4 vr = (p >= 0) ? ar[k4] : z;
                float4 vi = (p >= 0) ? ai[k4] : z;
                __half2 r01 = __floats2half2_rn(vr.x, vr.y);
                __half2 r23 = __floats2half2_rn(vr.z, vr.w);
                __half2 i01 = __floats2half2_rn(vi.x, vi.y);
                __half2 i23 = __floats2half2_rn(vi.z, vi.w);
                *(uint2*)(sm + OFF_A + 0*SEGA + base) = make_uint2(*(uint32_t*)&r01, *(uint32_t*)&r23);
                *(uint2*)(sm + OFF_A + 1*SEGA + base) = make_uint2(*(uint32_t*)&i01, *(uint32_t*)&i23);
            }
        }

        // ---- L2 prefetch of next tile's gathered rows ----
        {
            int ntile = tile + HALF_GRID;
            int grow = ntile*BM + row;
            if (ntile < T && grow < cnt) {
                int p2 = lst[grow];
                if (q < 4) {
                    const char* pr = (const char*)(img_re + (size_t)p2 * FD) + q*128;
                    asm volatile("prefetch.global.L2 [%0];" :: "l"(pr));
                } else {
                    const char* pi = (const char*)(img_im + (size_t)p2 * FD) + (q-4)*128;
                    asm volatile("prefetch.global.L2 [%0];" :: "l"(pi));
                }
            }
        }
        __syncthreads();

        // ---- compute: 3 acc sets, 4 n8-tiles each ----
        float T1[4][4], T2[4][4], T3[4][4];
        #pragma unroll
        for (int nt = 0; nt < 4; nt++)
            #pragma unroll
            for (int e = 0; e < 4; e++) { T1[nt][e] = 0.f; T2[nt][e] = 0.f; T3[nt][e] = 0.f; }

        #pragma unroll
        for (int ks = 0; ks < 8; ks++) {
            uint32_t axr[4], axi[4], as[4];
            {
                int rr = warp_m*16 + (lane & 15);
                int u  = 2*ks + (lane >> 4);
                uint32_t addr = smb + OFF_A + (uint32_t)(rr*256 + phys_unit(u, rr)*16);
                LDSM_X4(axr, addr);
                LDSM_X4(axi, addr + SEGA);
            }
            #pragma unroll
            for (int e = 0; e < 4; e++) {
                __half2 s = __hadd2(*(__half2*)&axr[e], *(__half2*)&axi[e]);
                as[e] = *(uint32_t*)&s;
            }
            uint32_t b[3][2][4];
            #pragma unroll
            for (int n2 = 0; n2 < 2; n2++) {
                int n = warp_n*32 + n2*16 + (lane & 7) + ((lane & 16) ? 8 : 0);
                int u = 2*ks + ((lane & 8) ? 1 : 0);
                uint32_t addr = smb + OFF_B + (uint32_t)(n*256 + phys_unit(u, n)*16);
                LDSM_X4(b[0][n2], addr);
                LDSM_X4(b[1][n2], addr + MATB);
                LDSM_X4(b[2][n2], addr + 2*MATB);
            }
            #pragma unroll
            for (int n2 = 0; n2 < 2; n2++) {
                mma4(T1[n2*2 + 0], as,  b[0][n2][0], b[0][n2][1]);
                mma4(T1[n2*2 + 1], as,  b[0][n2][2], b[0][n2][3]);
                mma4(T2[n2*2 + 0], axr, b[1][n2][0], b[1][n2][1]);
                mma4(T2[n2*2 + 1], axr, b[1][n2][2], b[1][n2][3]);
                mma4(T3[n2*2 + 0], axi, b[2][n2][0], b[2][n2][1]);
                mma4(T3[n2*2 + 1], axi, b[2][n2][2], b[2][n2][3]);
            }
        }

        // ---- fused epilogue: re=T1-T3, im=T1+T2 ----
        #pragma unroll
        for (int rv = 0; rv < 2; rv++) {
            int r = warp_m*16 + rv*8 + (lane >> 2);
            int grow = tile*BM + r;
            if (grow >= cnt) continue;
            int p = lst[grow];
            int ring = ring_of(p);
            const float* mre = g_mean_re + ring*FD;
            const float* mim = g_mean_im + ring*FD;
            float* op = out + (size_t)p * 256;
            #pragma unroll
            for (int nt = 0; nt < 4; nt++) {
                int c = warp_n*32 + nt*8 + (lane & 3)*2;
                float re0 = T1[nt][rv*2 + 0] - T3[nt][rv*2 + 0];
                float re1 = T1[nt][rv*2 + 1] - T3[nt][rv*2 + 1];
                float im0 = T1[nt][rv*2 + 0] + T2[nt][rv*2 + 0];
                float im1 = T1[nt][rv*2 + 1] + T2[nt][rv*2 + 1];
                float2 mr = *(const float2*)&mre[c];
                float2 mi = *(const float2*)&mim[c];
                float4 o;
                if (type == 0) {
                    o.x = 0.5f*(re0 + mr.x); o.y = 0.5f*(im0 + mi.x);
                    o.z = 0.5f*(re1 + mr.y); o.w = 0.5f*(im1 + mi.y);
                } else {
                    o.x = re0 - mr.x; o.y = im0 - mi.x;
                    o.z = re1 - mr.y; o.w = im1 - mi.y;
                }
                *(float4*)&op[c*2] = o;
            }
        }
    }
}

// ---------------- launch ----------------
extern "C" void kernel_launch(void* const* d_in, const int* in_sizes, int n_in,
                              void* d_out, int out_size) {
    const float* img_re = (const float*)d_in[0];
    const float* img_im = (const float*)d_in[1];
    const int*   mask   = (const int*)  d_in[2];
    const float* w1re   = (const float*)d_in[5];
    const float* w1im   = (const float*)d_in[6];
    const float* w2re   = (const float*)d_in[7];
    const float* w2im   = (const float*)d_in[8];
    float* out = (float*)d_out;

    k_prep<<<(2*FD*FD + 255)/256, 256>>>(w1re, w1im, w2re, w2im);
    k_count<<<NPIX/1024, 256>>>(mask);
    k_scan<<<1, 512>>>();
    k_scatter<<<NPIX/1024, 256>>>(mask);
    k_ringsum<<<dim3(NR, 8), 128>>>(img_re, img_im);
    k_ringmm<<<NR, 512>>>(w1re, w1im);

    cudaFuncSetAttribute(k_gemm, cudaFuncAttributeMaxDynamicSharedMemorySize, SMEM_TOTAL);
    k_gemm<<<GEMM_GRID, GEMM_THREADS, SMEM_TOTAL>>>(img_re, img_im, out);
}

// round 10
// speedup vs baseline: 1.1399x; 1.1399x over previous
#include <cuda_runtime.h>
#include <cuda_fp16.h>
#include <math.h>
#include <stdint.h>

#define HH    512
#define NPIX  (HH*HH)
#define FD    128
#define NR    363
#define BM    32
#define GEMM_THREADS 256
#define GEMM_GRID 296      // 2 per SM
#define HALF_GRID (GEMM_GRID/2)

// k_gemm smem layout (2 CTAs/SM) — R7 proven shape (~89KB, leaves ~50KB L1)
#define OFF_P    0                           // int[32]
#define OFF_RING 128                         // int[32]
#define OFF_A    1024                        // 3 segs: As(=Xr+Xi), Xr, Xi
#define SEGA     8192                        // 32 rows x 256B fp16
#define OFF_B    (OFF_A + 3*SEGA)            // 25600
#define MATB     32768                       // 128n x 256B fp16
#define SMEM_TOTAL (OFF_B + 2*MATB)          // 91136 (~89KB)

// ---------------- device scratch ----------------
__device__ float g_sum_re[NR*FD];
__device__ float g_sum_im[NR*FD];
__device__ float g_mean_re[NR*FD];
__device__ float g_mean_im[NR*FD];
__device__ int   g_rcount[NR];
__device__ int   g_ucnt[NR];
__device__ int   g_base[NR+1];     // uncor ring bases (for ringsum)
__device__ int   g_cur[2*NR];      // scatter cursors: [0,NR) uncor, [NR,2NR) cor
__device__ int   g_cnt[2];
__device__ int   g_list[2][NPIX];  // both lists ring-grouped
__device__ __align__(16) __half g_Wf[4][FD*FD];   // 0=w1re 1=w1im 2=w2re 3=w2im, [n*128+k]

// ---------------- helpers ----------------
__device__ __forceinline__ int ring_of(int p) {
    int i = (p >> 9) - 256;
    int j = (p & 511) - 256;
    int q = i*i + j*j;
    int s = __float2int_rd(sqrtf((float)q));
    while (s*s > q) --s;
    while ((s+1)*(s+1) <= q) ++s;
    return s;
}

__device__ __forceinline__ uint32_t smem_u32(const void* p) {
    uint32_t a;
    asm("{ .reg .u64 t; cvta.to.shared.u64 t, %1; cvt.u32.u64 %0, t; }" : "=r"(a) : "l"(p));
    return a;
}

// 16B-unit XOR swizzle within 256B rows
__device__ __forceinline__ int phys_unit(int u, int row) {
    return (u & 8) | ((u & 7) ^ (row & 7));
}

#define LDSM_X4(r, addr) \
    asm volatile("ldmatrix.sync.aligned.m8n8.x4.shared.b16 {%0,%1,%2,%3}, [%4];" \
        : "=r"((r)[0]), "=r"((r)[1]), "=r"((r)[2]), "=r"((r)[3]) : "r"(addr))

__device__ __forceinline__ void mma4(float* d, const uint32_t* a, uint32_t b0, uint32_t b1) {
    asm volatile("mma.sync.aligned.m16n8k16.row.col.f32.f16.f16.f32 "
        "{%0,%1,%2,%3}, {%4,%5,%6,%7}, {%8,%9}, {%0,%1,%2,%3};"
        : "+f"(d[0]), "+f"(d[1]), "+f"(d[2]), "+f"(d[3])
        : "r"(a[0]), "r"(a[1]), "r"(a[2]), "r"(a[3]), "r"(b0), "r"(b1));
}

// ---------------- merged zero + weight prep ----------------
__global__ void k_prep(const float* __restrict__ w1re, const float* __restrict__ w1im,
                       const float* __restrict__ w2re, const float* __restrict__ w2im) {
    int idx = blockIdx.x * blockDim.x + threadIdx.x;
    if (idx < NR) { g_rcount[idx] = 0; g_ucnt[idx] = 0; }
    if (idx >= 4*FD*FD) return;
    int mat = idx >> 14;
    int rem = idx & (FD*FD - 1);
    int n = rem >> 7, k = rem & 127;
    const float* W = (mat == 0) ? w1re : (mat == 1) ? w1im : (mat == 2) ? w2re : w2im;
    g_Wf[mat][n*FD + k] = __float2half_rn(W[k*FD + n]);
}

__global__ void k_count(const int* __restrict__ mask) {
    __shared__ int scnt[2*NR];
    int t = threadIdx.x;
    for (int i = t; i < 2*NR; i += 256) scnt[i] = 0;
    __syncthreads();
    int base = blockIdx.x * 1024;
    #pragma unroll
    for (int i = 0; i < 4; i++) {
        int p = base + i*256 + t;
        int r = ring_of(p);
        int m = mask[p];
        atomicAdd(&scnt[r], 1);
        if (m == 0) atomicAdd(&scnt[NR + r], 1);
    }
    __syncthreads();
    for (int i = t; i < NR; i += 256) {
        int c = scnt[i];       if (c) atomicAdd(&g_rcount[i], c);
        int u = scnt[NR + i];  if (u) atomicAdd(&g_ucnt[i], u);
    }
}

// two scans: uncor prefix (g_base/g_cur[0:NR]) and cor prefix (g_cur[NR:2NR])
__global__ void k_scan() {
    __shared__ int s[512];
    int t = threadIdx.x;
    // pass 1: uncor
    s[t] = (t < NR) ? g_ucnt[t] : 0;
    __syncthreads();
    #pragma unroll
    for (int d = 1; d < 512; d <<= 1) {
        int x = (t >= d) ? s[t - d] : 0;
        __syncthreads();
        s[t] += x;
        __syncthreads();
    }
    int ub = (t == 0) ? 0 : s[t - 1];
    int total_u = s[511];
    if (t < NR) { g_base[t] = ub; g_cur[t] = ub; }
    if (t == 0) {
        g_base[NR] = total_u;
        g_cnt[0]   = total_u;
        g_cnt[1]   = NPIX - total_u;
    }
    __syncthreads();
    // pass 2: cor (counts = rcount - ucnt)
    s[t] = (t < NR) ? (g_rcount[t] - g_ucnt[t]) : 0;
    __syncthreads();
    #pragma unroll
    for (int d = 1; d < 512; d <<= 1) {
        int x = (t >= d) ? s[t - d] : 0;
        __syncthreads();
        s[t] += x;
        __syncthreads();
    }
    int cb = (t == 0) ? 0 : s[t - 1];
    if (t < NR) g_cur[NR + t] = cb;
}

// scatter into ring-grouped lists, BOTH types bucketed by ring
__global__ void k_scatter(const int* __restrict__ mask) {
    __shared__ int lcnt[2*NR];
    __shared__ int sbase[2*NR];
    int t = threadIdx.x;
    for (int i = t; i < 2*NR; i += 256) lcnt[i] = 0;
    __syncthreads();
    int base = blockIdx.x * 1024;
    int key[4], lpos[4];
    #pragma unroll
    for (int i = 0; i < 4; i++) {
        int p = base + i*256 + t;
        int m = mask[p];
        key[i] = ring_of(p) + (m ? NR : 0);
        lpos[i] = atomicAdd(&lcnt[key[i]], 1);
    }
    __syncthreads();
    for (int i = t; i < 2*NR; i += 256) {
        int c = lcnt[i];
        if (c) sbase[i] = atomicAdd(&g_cur[i], c);
    }
    __syncthreads();
    #pragma unroll
    for (int i = 0; i < 4; i++) {
        int p = base + i*256 + t;
        int pos = sbase[key[i]] + lpos[i];
        if (key[i] >= NR) g_list[1][pos] = p;
        else              g_list[0][pos] = p;
    }
}

// atomic-free ring sums: grid (NR, 8), block 128
__global__ void k_ringsum(const float* __restrict__ img_re,
                          const float* __restrict__ img_im) {
    __shared__ float sred[4][32];
    int r = blockIdx.x, g = blockIdx.y;
    int t = threadIdx.x, lane = t & 31, wid = t >> 5;
    int b0 = g_base[r], n = g_base[r+1] - b0;
    const int* lst = g_list[0] + b0;
    float ar[16], ai[16];
    #pragma unroll
    for (int f = 0; f < 16; f++) { ar[f] = 0.f; ai[f] = 0.f; }
    for (int i = t; i < n; i += 128) {
        int p = lst[i];
        const float4* pr = (const float4*)(img_re + (size_t)p*FD + g*16);
        const float4* pi = (const float4*)(img_im + (size_t)p*FD + g*16);
        #pragma unroll
        for (int c = 0; c < 4; c++) {
            float4 v = pr[c];
            ar[c*4+0] += v.x; ar[c*4+1] += v.y; ar[c*4+2] += v.z; ar[c*4+3] += v.w;
            v = pi[c];
            ai[c*4+0] += v.x; ai[c*4+1] += v.y; ai[c*4+2] += v.z; ai[c*4+3] += v.w;
        }
    }
    #pragma unroll
    for (int f = 0; f < 16; f++) {
        #pragma unroll
        for (int m = 16; m > 0; m >>= 1) {
            ar[f] += __shfl_xor_sync(0xFFFFFFFF, ar[f], m);
            ai[f] += __shfl_xor_sync(0xFFFFFFFF, ai[f], m);
        }
    }
    if (lane == 0) {
        #pragma unroll
        for (int f = 0; f < 16; f++) {
            sred[wid][f]      = ar[f];
            sred[wid][16 + f] = ai[f];
        }
    }
    __syncthreads();
    if (t < 32) {
        float s = sred[0][t] + sred[1][t] + sred[2][t] + sred[3][t];
        int f = t & 15;
        if (t < 16) g_sum_re[r*FD + g*16 + f] = s;
        else        g_sum_im[r*FD + g*16 + f] = s;
    }
}

// ring means: block 512 = 4 k-slices x 128 features
__global__ void k_ringmm(const float* __restrict__ w1re,
                         const float* __restrict__ w1im) {
    __shared__ float sre[FD], sim[FD];
    __shared__ float pre[4][FD], pim[4][FD];
    int r = blockIdx.x, t = threadIdx.x;
    int sl = t >> 7, f = t & 127;
    if (t < 256) {
        if (t < 128) sre[t] = g_sum_re[r*FD + t];
        else         sim[t - 128] = g_sum_im[r*FD + t - 128];
    }
    __syncthreads();
    float accr = 0.f, acci = 0.f;
    #pragma unroll 8
    for (int kk = 0; kk < 32; kk++) {
        int k = sl*32 + kk;
        float wr = w1re[k*FD + f];
        float wi = w1im[k*FD + f];
        accr += sre[k]*wr - sim[k]*wi;
        acci += sre[k]*wi + sim[k]*wr;
    }
    pre[sl][f] = accr;
    pim[sl][f] = acci;
    __syncthreads();
    if (t < 256) {
        float c = (float)max(g_rcount[r], 1);
        int ff = t & 127;
        if (t < 128) g_mean_re[r*FD + ff] = (pre[0][ff]+pre[1][ff]+pre[2][ff]+pre[3][ff]) / c;
        else         g_mean_im[r*FD + ff] = (pim[0][ff]+pim[1][ff]+pim[2][ff]+pim[3][ff]) / c;
    }
}

// ---------------- main GEMM: Gauss 3-mult fp16 HMMA, BM=32, 2 CTA/SM (R7 proven) ----------------
// A segs: 0=As(Xr+Xi, fp32-summed then rounded), 1=Xr, 2=Xi
// B mats: 0=Wr, 1=Wi; combos Wi-Wr / Wi+Wr formed in registers per k-step.
// T1=As@Wr, T2=Xr@(Wi-Wr), T3=Xi@(Wi+Wr); re=T1-T3, im=T1+T2
__global__ __launch_bounds__(GEMM_THREADS, 2)
void k_gemm(const float* __restrict__ img_re, const float* __restrict__ img_im,
            float* __restrict__ out) {
    extern __shared__ char sm[];
    const int t = threadIdx.x, lane = t & 31, wid = t >> 5;
    const int warp_m = wid >> 2;          // 0..1 (16 rows each)
    const int warp_n = wid & 3;           // 0..3 (32 cols each)

    const int type  = (blockIdx.x >= HALF_GRID) ? 1 : 0;
    const int bid_t = type ? blockIdx.x - HALF_GRID : blockIdx.x;
    const int cnt   = g_cnt[type];
    const int T     = (cnt + BM - 1) >> 5;
    const int* lst  = g_list[type];

    uint32_t smb = smem_u32(sm);
    int* s_p    = (int*)(sm + OFF_P);
    int* s_ring = (int*)(sm + OFF_RING);

    const int row = t >> 3, q = t & 7;    // 8 threads per A row (32 rows)

    // ---- stage B: Wr, Wi fp16 transposed, swizzled (resident) ----
    {
        const __half* srcs[2] = { g_Wf[2*type], g_Wf[2*type+1] };
        #pragma unroll 4
        for (int i = t; i < 2*2048; i += GEMM_THREADS) {
            int mat = i >> 11, g = i & 2047;
            int n = g >> 4, u = g & 15;
            uint4 v = ((const uint4*)srcs[mat])[g];
            *(uint4*)(sm + OFF_B + mat*MATB + n*256 + phys_unit(u, n)*16) = v;
        }
    }

    for (int tile = bid_t; tile < T; tile += HALF_GRID) {
        __syncthreads();   // prev compute done before A rewrite

        // ---- stage A: batched gather loads, then convert+store ----
        {
            int grow = tile*BM + row;
            int p = -1, rg = 0;
            if (grow < cnt) { p = lst[grow]; rg = ring_of(p); }
            if (q == 0) { s_p[row] = p; s_ring[row] = rg; }
            const float4* ar = (const float4*)(img_re + (size_t)(p < 0 ? 0 : p) * FD);
            const float4* ai = (const float4*)(img_im + (size_t)(p < 0 ? 0 : p) * FD);
            float4 z = make_float4(0.f, 0.f, 0.f, 0.f);
            float4 vr[4], vi[4];
            #pragma unroll
            for (int i = 0; i < 4; i++) {
                vr[i] = (p >= 0) ? ar[q*4 + i] : z;
                vi[i] = (p >= 0) ? ai[q*4 + i] : z;
            }
            #pragma unroll
            for (int i = 0; i < 4; i++) {
                int k4 = q*4 + i;
                int u  = k4 >> 1;
                uint32_t base = (uint32_t)(row*256 + phys_unit(u, row)*16 + (k4 & 1)*8);
                __half2 r01 = __floats2half2_rn(vr[i].x, vr[i].y);
                __half2 r23 = __floats2half2_rn(vr[i].z, vr[i].w);
                __half2 i01 = __floats2half2_rn(vi[i].x, vi[i].y);
                __half2 i23 = __floats2half2_rn(vi[i].z, vi[i].w);
                __half2 s01 = __floats2half2_rn(vr[i].x + vi[i].x, vr[i].y + vi[i].y);
                __half2 s23 = __floats2half2_rn(vr[i].z + vi[i].z, vr[i].w + vi[i].w);
                *(uint2*)(sm + OFF_A + 0*SEGA + base) = make_uint2(*(uint32_t*)&s01, *(uint32_t*)&s23);
                *(uint2*)(sm + OFF_A + 1*SEGA + base) = make_uint2(*(uint32_t*)&r01, *(uint32_t*)&r23);
                *(uint2*)(sm + OFF_A + 2*SEGA + base) = make_uint2(*(uint32_t*)&i01, *(uint32_t*)&i23);
            }
        }

        // ---- L2 prefetch of next tile's gathered rows ----
        {
            int ntile = tile + HALF_GRID;
            int grow = ntile*BM + row;
            if (ntile < T && grow < cnt) {
                int p2 = lst[grow];
                if (q < 4) {
                    const char* pr = (const char*)(img_re + (size_t)p2 * FD) + q*128;
                    asm volatile("prefetch.global.L2 [%0];" :: "l"(pr));
                } else {
                    const char* pi = (const char*)(img_im + (size_t)p2 * FD) + (q-4)*128;
                    asm volatile("prefetch.global.L2 [%0];" :: "l"(pi));
                }
            }
        }
        __syncthreads();

        // ---- compute: 3 acc sets, 4 n8-tiles each ----
        float T1[4][4], T2[4][4], T3[4][4];
        #pragma unroll
        for (int nt = 0; nt < 4; nt++)
            #pragma unroll
            for (int e = 0; e < 4; e++) { T1[nt][e] = 0.f; T2[nt][e] = 0.f; T3[nt][e] = 0.f; }

        #pragma unroll
        for (int ks = 0; ks < 8; ks++) {
            uint32_t a[3][4];
            {
                int rr = warp_m*16 + (lane & 15);
                int u  = 2*ks + (lane >> 4);
                uint32_t addr = smb + OFF_A + (uint32_t)(rr*256 + phys_unit(u, rr)*16);
                LDSM_X4(a[0], addr);
                LDSM_X4(a[1], addr + SEGA);
                LDSM_X4(a[2], addr + 2*SEGA);
            }
            uint32_t b[2][2][4];
            #pragma unroll
            for (int n2 = 0; n2 < 2; n2++) {
                int n = warp_n*32 + n2*16 + (lane & 7) + ((lane & 16) ? 8 : 0);
                int u = 2*ks + ((lane & 8) ? 1 : 0);
                uint32_t addr = smb + OFF_B + (uint32_t)(n*256 + phys_unit(u, n)*16);
                LDSM_X4(b[0][n2], addr);
                LDSM_X4(b[1][n2], addr + MATB);
            }
            #pragma unroll
            for (int n2 = 0; n2 < 2; n2++) {
                uint32_t bm[4], bp[4];
                #pragma unroll
                for (int e = 0; e < 4; e++) {
                    __half2 wr = *(__half2*)&b[0][n2][e];
                    __half2 wi = *(__half2*)&b[1][n2][e];
                    __half2 m = __hsub2(wi, wr);
                    __half2 pl = __hadd2(wi, wr);
                    bm[e] = *(uint32_t*)&m;
                    bp[e] = *(uint32_t*)&pl;
                }
                mma4(T1[n2*2 + 0], a[0], b[0][n2][0], b[0][n2][1]);
                mma4(T1[n2*2 + 1], a[0], b[0][n2][2], b[0][n2][3]);
                mma4(T2[n2*2 + 0], a[1], bm[0], bm[1]);
                mma4(T2[n2*2 + 1], a[1], bm[2], bm[3]);
                mma4(T3[n2*2 + 0], a[2], bp[0], bp[1]);
                mma4(T3[n2*2 + 1], a[2], bp[2], bp[3]);
            }
        }

        // ---- fused epilogue: re=T1-T3, im=T1+T2 ----
        #pragma unroll
        for (int rv = 0; rv < 2; rv++) {
            int r = warp_m*16 + rv*8 + (lane >> 2);
            int p = s_p[r];
            if (p < 0) continue;
            int ring = s_ring[r];
            const float* mre = g_mean_re + ring*FD;
            const float* mim = g_mean_im + ring*FD;
            float* op = out + (size_t)p * 256;
            #pragma unroll
            for (int nt = 0; nt < 4; nt++) {
                int c = warp_n*32 + nt*8 + (lane & 3)*2;
                float re0 = T1[nt][rv*2 + 0] - T3[nt][rv*2 + 0];
                float re1 = T1[nt][rv*2 + 1] - T3[nt][rv*2 + 1];
                float im0 = T1[nt][rv*2 + 0] + T2[nt][rv*2 + 0];
                float im1 = T1[nt][rv*2 + 1] + T2[nt][rv*2 + 1];
                float2 mr = *(const float2*)&mre[c];
                float2 mi = *(const float2*)&mim[c];
                float4 o;
                if (type == 0) {
                    o.x = 0.5f*(re0 + mr.x); o.y = 0.5f*(im0 + mi.x);
                    o.z = 0.5f*(re1 + mr.y); o.w = 0.5f*(im1 + mi.y);
                } else {
                    o.x = re0 - mr.x; o.y = im0 - mi.x;
                    o.z = re1 - mr.y; o.w = im1 - mi.y;
                }
                *(float4*)&op[c*2] = o;
            }
        }
    }
}

// ---------------- launch ----------------
extern "C" void kernel_launch(void* const* d_in, const int* in_sizes, int n_in,
                              void* d_out, int out_size) {
    const float* img_re = (const float*)d_in[0];
    const float* img_im = (const float*)d_in[1];
    const int*   mask   = (const int*)  d_in[2];
    const float* w1re   = (const float*)d_in[5];
    const float* w1im   = (const float*)d_in[6];
    const float* w2re   = (const float*)d_in[7];
    const float* w2im   = (const float*)d_in[8];
    float* out = (float*)d_out;

    k_prep<<<(4*FD*FD + 255)/256, 256>>>(w1re, w1im, w2re, w2im);
    k_count<<<NPIX/1024, 256>>>(mask);
    k_scan<<<1, 512>>>();
    k_scatter<<<NPIX/1024, 256>>>(mask);
    k_ringsum<<<dim3(NR, 8), 128>>>(img_re, img_im);
    k_ringmm<<<NR, 512>>>(w1re, w1im);

    cudaFuncSetAttribute(k_gemm, cudaFuncAttributeMaxDynamicSharedMemorySize, SMEM_TOTAL);
    k_gemm<<<GEMM_GRID, GEMM_THREADS, SMEM_TOTAL>>>(img_re, img_im, out);
}